// round 3
// baseline (speedup 1.0000x reference)
#include <cuda_runtime.h>
#include <math.h>

#define NN 32768
#define EE 262144
#define BB 8
#define TWW 25
#define HH 128
#define LL 6

// ---------------- scratch (device globals; no allocation) ----------------
__device__ __align__(16) float g_h[NN*HH];
__device__ __align__(16) float g_t1[NN*HH];
__device__ __align__(16) float g_P[NN*HH];
__device__ __align__(16) float g_Q[NN*HH];
__device__ __align__(16) float g_R[NN*HH];
__device__ __align__(16) float g_agg[NN*HH];
__device__ float g_px[NN];
__device__ float g_pt[NN];
__device__ float g_cnt[NN];
__device__ float g_inv[NN];
__device__ float g_meanb[BB*HH];
__device__ float g_sqb[BB*HH];
__device__ float g_gcnt[BB];

__device__ __forceinline__ float swishf(float x) {
    return x / (1.f + __expf(-x));
}

// ---------------- zero kernels (graph-safe; no memset nodes on device globals) ----------------
__global__ void zero_prep() {
    int i = blockIdx.x * 256 + threadIdx.x;
    if (i < NN) g_cnt[i] = 0.f;
    if (i < BB) g_gcnt[i] = 0.f;
}

__global__ void zero_agg() {
    int i = blockIdx.x * 256 + threadIdx.x;   // over NN*HH/4
    ((float4*)g_agg)[i] = make_float4(0.f, 0.f, 0.f, 0.f);
}

__global__ void zero_stats() {
    int i = threadIdx.x + blockIdx.x * 256;
    if (i < BB*HH) { g_meanb[i] = 0.f; g_sqb[i] = 0.f; }
}

// ---------------- prep ----------------
__global__ void prep_node(const float* __restrict__ pos, const int* __restrict__ batch) {
    int i = blockIdx.x * 256 + threadIdx.x;
    if (i < NN) {
        g_pt[i] = pos[2*i]   * 0.25f;    // pos_t / TMAX
        g_px[i] = pos[2*i+1] * 0.0625f;  // (pos_x - 0) / 16
        atomicAdd(&g_gcnt[batch[i]], 1.f);
    }
}

__global__ void prep_edge(const int* __restrict__ eidx) {
    int e = blockIdx.x * 256 + threadIdx.x;
    if (e < EE) atomicAdd(&g_cnt[eidx[EE + e]], 1.f);
}

__global__ void fin_cnt() {
    int i = blockIdx.x * 256 + threadIdx.x;
    if (i < NN) g_inv[i] = 1.f / fmaxf(g_cnt[i], 1.f);
}

// ---------------- small per-node K<=27 kernels ----------------
// h1 = swish([u, px, pt] @ We1 + be1)
__global__ void encoder1(const float* __restrict__ u, const float* __restrict__ We1,
                         const float* __restrict__ be1) {
    __shared__ float s[27];
    int n = blockIdx.x;
    int t = threadIdx.x;
    if (t < 25)       s[t]  = u[n*25 + t];
    else if (t == 25) s[25] = g_px[n];
    else if (t == 26) s[26] = g_pt[n];
    __syncthreads();
    float a = __ldg(&be1[t]);
    #pragma unroll
    for (int k = 0; k < 27; k++) a += s[k] * __ldg(&We1[k*128 + t]);
    g_t1[n*128 + t] = swishf(a);
}

// R = u @ Wm1[l,256:281] + px * Wm1[l,281]
__global__ void rkern(const float* __restrict__ u, const float* __restrict__ Wm1l) {
    __shared__ float s[26];
    int n = blockIdx.x;
    int t = threadIdx.x;
    if (t < 25)       s[t]  = u[n*25 + t];
    else if (t == 25) s[25] = g_px[n];
    __syncthreads();
    float a = 0.f;
    #pragma unroll
    for (int k = 0; k < 25; k++) a += s[k] * __ldg(&Wm1l[(256+k)*128 + t]);
    a += s[25] * __ldg(&Wm1l[281*128 + t]);
    g_R[n*128 + t] = a;
}

// ---------------- generic tiled node GEMM: 64 rows x 128 cols ----------------
// modes:
//  0: out = swish(acc + bias)
//  1: out = acc + R + pt*wx + bias            (P)
//  2: out = acc - R                           (Q)
//  3: out = swish(acc + pt*wx + bias)         (update hidden; K=256, A2=agg scaled by inv_cnt)
//  4: out += swish(acc + bias)                (residual)
__global__ void mlp_tile(const float* __restrict__ A, const float* __restrict__ A2,
                         const float* __restrict__ W, const float* __restrict__ bias,
                         const float* __restrict__ Rm, const float* __restrict__ wx,
                         float* __restrict__ out, int K, int mode) {
    __shared__ __align__(16) float As[64*33];
    __shared__ __align__(16) float Ws[32*128];
    int tid = threadIdx.x;
    int tx = tid & 31, ty = tid >> 5;
    int r0 = blockIdx.x * 64;

    float acc[8][4];
    #pragma unroll
    for (int j = 0; j < 8; j++)
        #pragma unroll
        for (int i = 0; i < 4; i++) acc[j][i] = 0.f;

    for (int kt = 0; kt < K; kt += 32) {
        // A tile: 64 x 32
        #pragma unroll
        for (int idx = tid; idx < 64*32; idx += 256) {
            int r = idx >> 5, kk = idx & 31;
            int row = r0 + r, k = kt + kk;
            float v;
            if (k < 128) v = A[row*128 + k];
            else         v = A2[row*128 + (k - 128)] * g_inv[row];
            As[r*33 + kk] = v;
        }
        // W tile: 32 x 128
        #pragma unroll
        for (int idx = tid; idx < 32*128; idx += 256) {
            int kk = idx >> 7, c = idx & 127;
            Ws[idx] = W[(kt + kk)*128 + c];
        }
        __syncthreads();
        #pragma unroll 8
        for (int kk = 0; kk < 32; kk++) {
            float4 w = *(const float4*)&Ws[kk*128 + tx*4];
            #pragma unroll
            for (int j = 0; j < 8; j++) {
                float a = As[(ty*8 + j)*33 + kk];
                acc[j][0] += a * w.x;
                acc[j][1] += a * w.y;
                acc[j][2] += a * w.z;
                acc[j][3] += a * w.w;
            }
        }
        __syncthreads();
    }

    int c0 = tx * 4;
    #pragma unroll
    for (int j = 0; j < 8; j++) {
        int row = r0 + ty*8 + j;
        float o[4];
        #pragma unroll
        for (int i = 0; i < 4; i++) {
            int c = c0 + i;
            float a = acc[j][i];
            if (mode == 0) {
                o[i] = swishf(a + __ldg(&bias[c]));
            } else if (mode == 1) {
                o[i] = a + Rm[row*128 + c] + g_pt[row]*__ldg(&wx[c]) + __ldg(&bias[c]);
            } else if (mode == 2) {
                o[i] = a - Rm[row*128 + c];
            } else if (mode == 3) {
                o[i] = swishf(a + g_pt[row]*__ldg(&wx[c]) + __ldg(&bias[c]));
            } else {
                o[i] = out[row*128 + c] + swishf(a + __ldg(&bias[c]));
            }
        }
        *(float4*)&out[row*128 + c0] = make_float4(o[0], o[1], o[2], o[3]);
    }
}

// ---------------- fused edge kernel ----------------
// msg = swish(P[tgt] + Q[src]);  out = swish(msg @ Wm2 + bm2);  agg[tgt] += out
#define EDGE_SMEM ((128*128 + 64*128)*4 + 64*2*4)
__global__ void edge_kernel(const int* __restrict__ eidx,
                            const float* __restrict__ Wm2l,
                            const float* __restrict__ bm2l) {
    extern __shared__ __align__(16) float sm[];
    float* Ws = sm;                       // 128x128
    float* Ms = sm + 128*128;             // 64x128
    int*   et = (int*)(sm + 128*128 + 64*128);
    int*   es = et + 64;

    int tid = threadIdx.x;
    int e0 = blockIdx.x * 64;

    for (int i = tid; i < 128*128; i += 256) Ws[i] = Wm2l[i];
    if (tid < 64) {
        es[tid] = eidx[e0 + tid];        // src row
        et[tid] = eidx[EE + e0 + tid];   // tgt row
    }
    __syncthreads();

    // phase 1: gather + first swish
    for (int idx = tid; idx < 64*128; idx += 256) {
        int e = idx >> 7, c = idx & 127;
        float pre = g_P[et[e]*128 + c] + g_Q[es[e]*128 + c];
        Ms[idx] = swishf(pre);
    }
    __syncthreads();

    // phase 2: 64x128x128 GEMM
    int tx = tid & 31, ty = tid >> 5;
    float acc[8][4];
    #pragma unroll
    for (int j = 0; j < 8; j++)
        #pragma unroll
        for (int i = 0; i < 4; i++) acc[j][i] = 0.f;

    #pragma unroll 8
    for (int kk = 0; kk < 128; kk++) {
        float4 w = *(const float4*)&Ws[kk*128 + tx*4];
        #pragma unroll
        for (int j = 0; j < 8; j++) {
            float a = Ms[(ty*8 + j)*128 + kk];
            acc[j][0] += a * w.x;
            acc[j][1] += a * w.y;
            acc[j][2] += a * w.z;
            acc[j][3] += a * w.w;
        }
    }

    // phase 3: second swish + scatter-add
    int c0 = tx * 4;
    #pragma unroll
    for (int j = 0; j < 8; j++) {
        int e = ty*8 + j;
        int t = et[e];
        #pragma unroll
        for (int i = 0; i < 4; i++) {
            float x = acc[j][i] + __ldg(&bm2l[c0 + i]);
            atomicAdd(&g_agg[t*128 + c0 + i], swishf(x));
        }
    }
}

// ---------------- per-batch norm ----------------
__global__ void norm_reduce(const int* __restrict__ batch) {
    int c = threadIdx.x;              // 128 features
    int base = blockIdx.x * 128;      // 128 nodes (4096-aligned segments)
    float s = 0.f, q = 0.f;
    for (int r = 0; r < 128; r++) {
        float v = g_h[(base + r)*128 + c];
        s += v; q += v*v;
    }
    int b = batch[base];
    atomicAdd(&g_meanb[b*128 + c], s);
    atomicAdd(&g_sqb[b*128 + c], q);
}

__global__ void norm_apply(const int* __restrict__ batch) {
    int i = blockIdx.x * 256 + threadIdx.x;   // over N*128
    int node = i >> 7, c = i & 127;
    int b = batch[node];
    float gi = 1.f / g_gcnt[b];
    float m = g_meanb[b*128 + c] * gi;
    float var = g_sqb[b*128 + c] * gi - m*m;
    g_h[i] = (g_h[i] - m) * rsqrtf(var + 1e-5f);
}

// ---------------- conv decoder ----------------
__global__ void decoder(const float* __restrict__ u,
                        const float* __restrict__ Wc1, const float* __restrict__ bc1,
                        const float* __restrict__ Wc2, const float* __restrict__ bc2,
                        float* __restrict__ out) {
    __shared__ float hr[128];
    __shared__ float c1[8*38];
    int n = blockIdx.x;
    int tid = threadIdx.x;   // 64 threads
    for (int i = tid; i < 128; i += 64) hr[i] = g_h[n*128 + i];
    __syncthreads();
    for (int i = tid; i < 8*38; i += 64) {
        int ch = i / 38, p = i % 38;
        float a = __ldg(&bc1[ch]);
        #pragma unroll
        for (int k = 0; k < 16; k++) a += hr[3*p + k] * __ldg(&Wc1[ch*16 + k]);
        c1[i] = swishf(a);
    }
    __syncthreads();
    if (tid < 25) {
        float a = __ldg(&bc2[0]);
        #pragma unroll
        for (int c = 0; c < 8; c++)
            #pragma unroll
            for (int k = 0; k < 14; k++)
                a += c1[c*38 + tid + k] * __ldg(&Wc2[c*14 + k]);
        float dt = 4.0f / 250.0f;
        out[n*25 + tid] = u[n*25 + 24] + (float)(tid + 1) * dt * a;
    }
}

// ---------------- host ----------------
extern "C" void kernel_launch(void* const* d_in, const int* in_sizes, int n_in,
                              void* d_out, int out_size) {
    const float* u     = (const float*)d_in[0];
    const float* pos   = (const float*)d_in[1];
    const int*   eidx  = (const int*)d_in[2];
    const int*   batch = (const int*)d_in[3];
    const float* We1 = (const float*)d_in[4];
    const float* be1 = (const float*)d_in[5];
    const float* We2 = (const float*)d_in[6];
    const float* be2 = (const float*)d_in[7];
    const float* Wm1 = (const float*)d_in[8];
    const float* bm1 = (const float*)d_in[9];
    const float* Wm2 = (const float*)d_in[10];
    const float* bm2 = (const float*)d_in[11];
    const float* Wu1 = (const float*)d_in[12];
    const float* bu1 = (const float*)d_in[13];
    const float* Wu2 = (const float*)d_in[14];
    const float* bu2 = (const float*)d_in[15];
    const float* Wc1 = (const float*)d_in[16];
    const float* bc1 = (const float*)d_in[17];
    const float* Wc2 = (const float*)d_in[18];
    const float* bc2 = (const float*)d_in[19];
    float* out = (float*)d_out;

    void *a_h, *a_t1, *a_P, *a_Q, *a_R, *a_agg;
    cudaGetSymbolAddress(&a_h,   g_h);
    cudaGetSymbolAddress(&a_t1,  g_t1);
    cudaGetSymbolAddress(&a_P,   g_P);
    cudaGetSymbolAddress(&a_Q,   g_Q);
    cudaGetSymbolAddress(&a_R,   g_R);
    cudaGetSymbolAddress(&a_agg, g_agg);
    float* h   = (float*)a_h;
    float* t1  = (float*)a_t1;
    float* P   = (float*)a_P;
    float* Q   = (float*)a_Q;
    float* R   = (float*)a_R;
    float* agg = (float*)a_agg;

    cudaFuncSetAttribute(edge_kernel, cudaFuncAttributeMaxDynamicSharedMemorySize, EDGE_SMEM);

    zero_prep<<<NN/256, 256>>>();
    prep_node<<<NN/256, 256>>>(pos, batch);
    prep_edge<<<EE/256, 256>>>(eidx);
    fin_cnt<<<NN/256, 256>>>();

    encoder1<<<NN, 128>>>(u, We1, be1);
    mlp_tile<<<NN/64, 256>>>(t1, nullptr, We2, be2, nullptr, nullptr, h, 128, 0);

    for (int l = 0; l < LL; l++) {
        const float* Wm1l = Wm1 + (size_t)l * 283 * 128;
        const float* Wu1l = Wu1 + (size_t)l * 257 * 128;
        const float* Wm2l = Wm2 + (size_t)l * 128 * 128;
        const float* Wu2l = Wu2 + (size_t)l * 128 * 128;

        rkern<<<NN, 128>>>(u, Wm1l);
        // P = h@Wa + R + pt*wv + bm1
        mlp_tile<<<NN/64, 256>>>(h, nullptr, Wm1l, bm1 + l*128, R, Wm1l + 282*128, P, 128, 1);
        // Q = h@Wb - R
        mlp_tile<<<NN/64, 256>>>(h, nullptr, Wm1l + 128*128, nullptr, R, nullptr, Q, 128, 2);

        zero_agg<<<(NN*HH/4)/256, 256>>>();
        edge_kernel<<<EE/64, 256, EDGE_SMEM>>>(eidx, Wm2l, bm2 + l*128);

        // hidden = swish(h@W1 + (agg*inv)@W2 + pt*w3 + bu1)
        mlp_tile<<<NN/64, 256>>>(h, agg, Wu1l, bu1 + l*128, nullptr, Wu1l + 256*128, t1, 256, 3);
        // h += swish(hidden@Wu2 + bu2)
        mlp_tile<<<NN/64, 256>>>(t1, nullptr, Wu2l, bu2 + l*128, nullptr, nullptr, h, 128, 4);

        zero_stats<<<(BB*HH + 255)/256, 256>>>();
        norm_reduce<<<NN/128, 128>>>(batch);
        norm_apply<<<(NN*HH)/256, 256>>>(batch);
    }

    decoder<<<NN, 64>>>(u, Wc1, bc1, Wc2, bc2, out);
}

// round 6
// speedup vs baseline: 2.4700x; 2.4700x over previous
#include <cuda_runtime.h>
#include <cuda_fp16.h>
#include <cstdint>
#include <math.h>

typedef unsigned int u32;

#define NN 32768
#define EE 262144
#define BB 8
#define HH 128
#define LL 6

// ---------------- scratch (device globals; no allocation) ----------------
__device__ __align__(16) float g_h[NN*HH];
__device__ __align__(16) float g_t1[NN*HH];
__device__ __align__(16) float g_P[NN*HH];
__device__ __align__(16) float g_Q[NN*HH];
__device__ __align__(16) float g_R[NN*HH];
__device__ __align__(16) float g_agg[NN*HH];
__device__ float g_px[NN];
__device__ float g_pt[NN];
__device__ float g_cnt[NN];
__device__ float g_inv[NN];
__device__ float g_meanb[BB*HH];
__device__ float g_sqb[BB*HH];
__device__ float g_gcnt[BB];

__device__ __forceinline__ float swishf(float x) {
    return x / (1.f + __expf(-x));
}

__device__ __forceinline__ u32 smem_u32(const void* p) {
    return (u32)__cvta_generic_to_shared(p);
}

__device__ __forceinline__ void ldsm4(u32& r0, u32& r1, u32& r2, u32& r3, u32 a) {
    asm volatile("ldmatrix.sync.aligned.m8n8.x4.shared.b16 {%0,%1,%2,%3}, [%4];"
                 : "=r"(r0), "=r"(r1), "=r"(r2), "=r"(r3) : "r"(a));
}

__device__ __forceinline__ void ldsm4t(u32& r0, u32& r1, u32& r2, u32& r3, u32 a) {
    asm volatile("ldmatrix.sync.aligned.m8n8.x4.trans.shared.b16 {%0,%1,%2,%3}, [%4];"
                 : "=r"(r0), "=r"(r1), "=r"(r2), "=r"(r3) : "r"(a));
}

__device__ __forceinline__ void mma16816(float* c, u32 a0, u32 a1, u32 a2, u32 a3,
                                         u32 b0, u32 b1) {
    asm volatile("mma.sync.aligned.m16n8k16.row.col.f32.f16.f16.f32 "
                 "{%0,%1,%2,%3}, {%4,%5,%6,%7}, {%8,%9}, {%0,%1,%2,%3};"
                 : "+f"(c[0]), "+f"(c[1]), "+f"(c[2]), "+f"(c[3])
                 : "r"(a0), "r"(a1), "r"(a2), "r"(a3), "r"(b0), "r"(b1));
}

// ---------------- zero kernels ----------------
__global__ void zero_prep() {
    int i = blockIdx.x * 256 + threadIdx.x;
    if (i < NN) g_cnt[i] = 0.f;
    if (i < BB) g_gcnt[i] = 0.f;
}

__global__ void zero_agg() {
    int i = blockIdx.x * 256 + threadIdx.x;
    ((float4*)g_agg)[i] = make_float4(0.f, 0.f, 0.f, 0.f);
}

__global__ void zero_stats() {
    int i = threadIdx.x + blockIdx.x * 256;
    if (i < BB*HH) { g_meanb[i] = 0.f; g_sqb[i] = 0.f; }
}

// ---------------- prep ----------------
__global__ void prep_node(const float* __restrict__ pos, const int* __restrict__ batch) {
    int i = blockIdx.x * 256 + threadIdx.x;
    if (i < NN) {
        g_pt[i] = pos[2*i]   * 0.25f;
        g_px[i] = pos[2*i+1] * 0.0625f;
        atomicAdd(&g_gcnt[batch[i]], 1.f);
    }
}

__global__ void prep_edge(const int* __restrict__ eidx) {
    int e = blockIdx.x * 256 + threadIdx.x;
    if (e < EE) atomicAdd(&g_cnt[eidx[EE + e]], 1.f);
}

__global__ void fin_cnt() {
    int i = blockIdx.x * 256 + threadIdx.x;
    if (i < NN) g_inv[i] = 1.f / fmaxf(g_cnt[i], 1.f);
}

// ---------------- small per-node kernels ----------------
__global__ void encoder1(const float* __restrict__ u, const float* __restrict__ We1,
                         const float* __restrict__ be1) {
    __shared__ float s[27];
    int n = blockIdx.x;
    int t = threadIdx.x;
    if (t < 25)       s[t]  = u[n*25 + t];
    else if (t == 25) s[25] = g_px[n];
    else if (t == 26) s[26] = g_pt[n];
    __syncthreads();
    float a = __ldg(&be1[t]);
    #pragma unroll
    for (int k = 0; k < 27; k++) a += s[k] * __ldg(&We1[k*128 + t]);
    g_t1[n*128 + t] = swishf(a);
}

__global__ void rkern(const float* __restrict__ u, const float* __restrict__ Wm1l) {
    __shared__ float s[26];
    int n = blockIdx.x;
    int t = threadIdx.x;
    if (t < 25)       s[t]  = u[n*25 + t];
    else if (t == 25) s[25] = g_px[n];
    __syncthreads();
    float a = 0.f;
    #pragma unroll
    for (int k = 0; k < 25; k++) a += s[k] * __ldg(&Wm1l[(256+k)*128 + t]);
    a += s[25] * __ldg(&Wm1l[281*128 + t]);
    g_R[n*128 + t] = a;
}

// ---------------- tensor-core node GEMM: 64 rows x 128 cols ----------------
// modes: 0: swish(acc+b)  1: acc+R+pt*wx+b  2: acc-R
//        3: swish(acc+pt*wx+b) [K=256, A2 scaled by inv]  4: out += swish(acc+b)
__global__ void mlp16(const float* __restrict__ A, const float* __restrict__ A2,
                      const float* __restrict__ W, const float* __restrict__ bias,
                      const float* __restrict__ Rm, const float* __restrict__ wx,
                      float* __restrict__ out, int K, int mode) {
    extern __shared__ __align__(16) char smbuf[];
    __half* Wh = (__half*)smbuf;            // K x 136
    __half* Ah = Wh + K*136;                // 64 x (K+8)
    const int PA = K + 8;

    int tid = threadIdx.x;
    int r0g = blockIdx.x * 64;

    // stage W (K x 128 fp32 -> fp16), pitch 136
    for (int i = tid; i < K*32; i += 256) {
        int k = i >> 5;
        int c4 = (i & 31) << 2;
        float4 v = *(const float4*)&W[k*128 + c4];
        __half2* dst = (__half2*)&Wh[k*136 + c4];
        dst[0] = __floats2half2_rn(v.x, v.y);
        dst[1] = __floats2half2_rn(v.z, v.w);
    }
    // stage A (64 x K), pitch PA
    int kq = K >> 2;                 // float4 groups per row
    int sh = (K == 256) ? 6 : 5;     // log2(kq)
    for (int i = tid; i < (64 << sh); i += 256) {
        int r  = i >> sh;
        int k4 = (i & (kq - 1)) << 2;
        int row = r0g + r;
        float4 v;
        if (k4 < 128) {
            v = *(const float4*)&A[row*128 + k4];
        } else {
            v = *(const float4*)&A2[row*128 + (k4 - 128)];
            float s = g_inv[row];
            v.x *= s; v.y *= s; v.z *= s; v.w *= s;
        }
        __half2* dst = (__half2*)&Ah[r*PA + k4];
        dst[0] = __floats2half2_rn(v.x, v.y);
        dst[1] = __floats2half2_rn(v.z, v.w);
    }
    __syncthreads();

    int w = tid >> 5;
    int lane = tid & 31;
    int wm = (w & 3) * 16;
    int wn = (w >> 2) * 64;
    int grp = lane >> 2;
    int qt  = lane & 3;
    int lr = lane & 7;
    int lm = lane >> 3;

    float acc[8][4];
    #pragma unroll
    for (int j = 0; j < 8; j++) {
        #pragma unroll
        for (int i = 0; i < 4; i++) acc[j][i] = 0.f;
    }

    u32 a_base = smem_u32(Ah) + (u32)(((wm + (lm & 1)*8 + lr)*PA + (lm >> 1)*8) * 2);
    u32 b_base = smem_u32(Wh) + (u32)((((lm & 1)*8 + lr)*136 + wn + (lm >> 1)*8) * 2);

    int kit = K >> 4;
    for (int kk = 0; kk < kit; kk++) {
        u32 a0, a1, a2, a3;
        ldsm4(a0, a1, a2, a3, a_base + (u32)(kk*32));
        #pragma unroll
        for (int j = 0; j < 4; j++) {
            u32 b0, b1, b2, b3;
            ldsm4t(b0, b1, b2, b3, b_base + (u32)(kk*4352 + j*32));
            mma16816(acc[2*j],     a0, a1, a2, a3, b0, b1);
            mma16816(acc[2*j + 1], a0, a1, a2, a3, b2, b3);
        }
    }

    // epilogue
    #pragma unroll
    for (int j = 0; j < 8; j++) {
        int col = wn + j*8 + 2*qt;
        int r0 = r0g + wm + grp;
        int r1 = r0 + 8;
        float o0, o1, o2, o3;
        float a0 = acc[j][0], a1 = acc[j][1], a2 = acc[j][2], a3 = acc[j][3];
        if (mode == 0) {
            o0 = swishf(a0 + __ldg(&bias[col]));
            o1 = swishf(a1 + __ldg(&bias[col+1]));
            o2 = swishf(a2 + __ldg(&bias[col]));
            o3 = swishf(a3 + __ldg(&bias[col+1]));
        } else if (mode == 1) {
            float pt0 = g_pt[r0], pt1 = g_pt[r1];
            o0 = a0 + Rm[r0*128 + col]   + pt0*__ldg(&wx[col])   + __ldg(&bias[col]);
            o1 = a1 + Rm[r0*128 + col+1] + pt0*__ldg(&wx[col+1]) + __ldg(&bias[col+1]);
            o2 = a2 + Rm[r1*128 + col]   + pt1*__ldg(&wx[col])   + __ldg(&bias[col]);
            o3 = a3 + Rm[r1*128 + col+1] + pt1*__ldg(&wx[col+1]) + __ldg(&bias[col+1]);
        } else if (mode == 2) {
            o0 = a0 - Rm[r0*128 + col];
            o1 = a1 - Rm[r0*128 + col+1];
            o2 = a2 - Rm[r1*128 + col];
            o3 = a3 - Rm[r1*128 + col+1];
        } else if (mode == 3) {
            float pt0 = g_pt[r0], pt1 = g_pt[r1];
            o0 = swishf(a0 + pt0*__ldg(&wx[col])   + __ldg(&bias[col]));
            o1 = swishf(a1 + pt0*__ldg(&wx[col+1]) + __ldg(&bias[col+1]));
            o2 = swishf(a2 + pt1*__ldg(&wx[col])   + __ldg(&bias[col]));
            o3 = swishf(a3 + pt1*__ldg(&wx[col+1]) + __ldg(&bias[col+1]));
        } else {
            o0 = out[r0*128 + col]   + swishf(a0 + __ldg(&bias[col]));
            o1 = out[r0*128 + col+1] + swishf(a1 + __ldg(&bias[col+1]));
            o2 = out[r1*128 + col]   + swishf(a2 + __ldg(&bias[col]));
            o3 = out[r1*128 + col+1] + swishf(a3 + __ldg(&bias[col+1]));
        }
        *(float2*)&out[r0*128 + col] = make_float2(o0, o1);
        *(float2*)&out[r1*128 + col] = make_float2(o2, o3);
    }
}

// ---------------- fused edge kernel (fp16 mma) ----------------
#define EDGE_SMEM ((128*136 + 64*136)*2 + 64*2*4)
__global__ void edge_kernel(const int* __restrict__ eidx,
                            const float* __restrict__ Wm2l,
                            const float* __restrict__ bm2l) {
    extern __shared__ __align__(16) char smbuf[];
    __half* Wh = (__half*)smbuf;            // 128 x 136
    __half* Mh = Wh + 128*136;              // 64 x 136
    int* et = (int*)(Mh + 64*136);
    int* es = et + 64;

    int tid = threadIdx.x;
    int e0 = blockIdx.x * 64;

    for (int i = tid; i < 128*32; i += 256) {
        int k = i >> 5;
        int c4 = (i & 31) << 2;
        float4 v = *(const float4*)&Wm2l[k*128 + c4];
        __half2* dst = (__half2*)&Wh[k*136 + c4];
        dst[0] = __floats2half2_rn(v.x, v.y);
        dst[1] = __floats2half2_rn(v.z, v.w);
    }
    if (tid < 64) {
        es[tid] = eidx[e0 + tid];
        et[tid] = eidx[EE + e0 + tid];
    }
    __syncthreads();

    for (int i = tid; i < 64*32; i += 256) {
        int e = i >> 5;
        int c4 = (i & 31) << 2;
        float4 p = *(const float4*)&g_P[et[e]*128 + c4];
        float4 q = *(const float4*)&g_Q[es[e]*128 + c4];
        __half2* dst = (__half2*)&Mh[e*136 + c4];
        dst[0] = __floats2half2_rn(swishf(p.x + q.x), swishf(p.y + q.y));
        dst[1] = __floats2half2_rn(swishf(p.z + q.z), swishf(p.w + q.w));
    }
    __syncthreads();

    int w = tid >> 5;
    int lane = tid & 31;
    int wm = (w & 3) * 16;
    int wn = (w >> 2) * 64;
    int grp = lane >> 2;
    int qt  = lane & 3;
    int lr = lane & 7;
    int lm = lane >> 3;

    float acc[8][4];
    #pragma unroll
    for (int j = 0; j < 8; j++) {
        #pragma unroll
        for (int i = 0; i < 4; i++) acc[j][i] = 0.f;
    }

    u32 a_base = smem_u32(Mh) + (u32)(((wm + (lm & 1)*8 + lr)*136 + (lm >> 1)*8) * 2);
    u32 b_base = smem_u32(Wh) + (u32)((((lm & 1)*8 + lr)*136 + wn + (lm >> 1)*8) * 2);

    #pragma unroll
    for (int kk = 0; kk < 8; kk++) {
        u32 a0, a1, a2, a3;
        ldsm4(a0, a1, a2, a3, a_base + (u32)(kk*32));
        #pragma unroll
        for (int j = 0; j < 4; j++) {
            u32 b0, b1, b2, b3;
            ldsm4t(b0, b1, b2, b3, b_base + (u32)(kk*4352 + j*32));
            mma16816(acc[2*j],     a0, a1, a2, a3, b0, b1);
            mma16816(acc[2*j + 1], a0, a1, a2, a3, b2, b3);
        }
    }

    int er0 = wm + grp;
    int er1 = er0 + 8;
    int t0 = et[er0];
    int t1 = et[er1];
    #pragma unroll
    for (int j = 0; j < 8; j++) {
        int col = wn + j*8 + 2*qt;
        float b0v = __ldg(&bm2l[col]);
        float b1v = __ldg(&bm2l[col + 1]);
        atomicAdd(&g_agg[t0*128 + col],     swishf(acc[j][0] + b0v));
        atomicAdd(&g_agg[t0*128 + col + 1], swishf(acc[j][1] + b1v));
        atomicAdd(&g_agg[t1*128 + col],     swishf(acc[j][2] + b0v));
        atomicAdd(&g_agg[t1*128 + col + 1], swishf(acc[j][3] + b1v));
    }
}

// ---------------- per-batch norm ----------------
__global__ void norm_reduce(const int* __restrict__ batch) {
    int c = threadIdx.x;
    int base = blockIdx.x * 128;
    float s = 0.f, q = 0.f;
    for (int r = 0; r < 128; r++) {
        float v = g_h[(base + r)*128 + c];
        s += v;
        q += v*v;
    }
    int b = batch[base];
    atomicAdd(&g_meanb[b*128 + c], s);
    atomicAdd(&g_sqb[b*128 + c], q);
}

__global__ void norm_apply(const int* __restrict__ batch) {
    int i = blockIdx.x * 256 + threadIdx.x;
    int node = i >> 7;
    int c = i & 127;
    int b = batch[node];
    float gi = 1.f / g_gcnt[b];
    float m = g_meanb[b*128 + c] * gi;
    float var = g_sqb[b*128 + c] * gi - m*m;
    g_h[i] = (g_h[i] - m) * rsqrtf(var + 1e-5f);
}

// ---------------- conv decoder ----------------
__global__ void decoder(const float* __restrict__ u,
                        const float* __restrict__ Wc1, const float* __restrict__ bc1,
                        const float* __restrict__ Wc2, const float* __restrict__ bc2,
                        float* __restrict__ out) {
    __shared__ float hr[128];
    __shared__ float c1[8*38];
    int n = blockIdx.x;
    int tid = threadIdx.x;
    for (int i = tid; i < 128; i += 64) hr[i] = g_h[n*128 + i];
    __syncthreads();
    for (int i = tid; i < 8*38; i += 64) {
        int ch = i / 38;
        int p = i % 38;
        float a = __ldg(&bc1[ch]);
        #pragma unroll
        for (int k = 0; k < 16; k++) a += hr[3*p + k] * __ldg(&Wc1[ch*16 + k]);
        c1[i] = swishf(a);
    }
    __syncthreads();
    if (tid < 25) {
        float a = __ldg(&bc2[0]);
        #pragma unroll
        for (int c = 0; c < 8; c++) {
            #pragma unroll
            for (int k = 0; k < 14; k++)
                a += c1[c*38 + tid + k] * __ldg(&Wc2[c*14 + k]);
        }
        float dt = 4.0f / 250.0f;
        out[n*25 + tid] = u[n*25 + 24] + (float)(tid + 1) * dt * a;
    }
}

// ---------------- host ----------------
extern "C" void kernel_launch(void* const* d_in, const int* in_sizes, int n_in,
                              void* d_out, int out_size) {
    const float* u     = (const float*)d_in[0];
    const float* pos   = (const float*)d_in[1];
    const int*   eidx  = (const int*)d_in[2];
    const int*   batch = (const int*)d_in[3];
    const float* We1 = (const float*)d_in[4];
    const float* be1 = (const float*)d_in[5];
    const float* We2 = (const float*)d_in[6];
    const float* be2 = (const float*)d_in[7];
    const float* Wm1 = (const float*)d_in[8];
    const float* bm1 = (const float*)d_in[9];
    const float* Wm2 = (const float*)d_in[10];
    const float* bm2 = (const float*)d_in[11];
    const float* Wu1 = (const float*)d_in[12];
    const float* bu1 = (const float*)d_in[13];
    const float* Wu2 = (const float*)d_in[14];
    const float* bu2 = (const float*)d_in[15];
    const float* Wc1 = (const float*)d_in[16];
    const float* bc1 = (const float*)d_in[17];
    const float* Wc2 = (const float*)d_in[18];
    const float* bc2 = (const float*)d_in[19];
    float* out = (float*)d_out;

    void *a_h = 0, *a_t1 = 0, *a_P = 0, *a_Q = 0, *a_R = 0, *a_agg = 0;
    cudaGetSymbolAddress(&a_h,   g_h);
    cudaGetSymbolAddress(&a_t1,  g_t1);
    cudaGetSymbolAddress(&a_P,   g_P);
    cudaGetSymbolAddress(&a_Q,   g_Q);
    cudaGetSymbolAddress(&a_R,   g_R);
    cudaGetSymbolAddress(&a_agg, g_agg);
    float* h   = (float*)a_h;
    float* t1  = (float*)a_t1;
    float* P   = (float*)a_P;
    float* Q   = (float*)a_Q;
    float* R   = (float*)a_R;
    float* agg = (float*)a_agg;

    int MLP_SMEM_MAX = (256*136 + 64*264) * 2;   // K=256 case
    int MLP_SMEM_128 = (128*136 + 64*136) * 2;
    cudaFuncSetAttribute(mlp16, cudaFuncAttributeMaxDynamicSharedMemorySize, MLP_SMEM_MAX);
    cudaFuncSetAttribute(edge_kernel, cudaFuncAttributeMaxDynamicSharedMemorySize, EDGE_SMEM);

    zero_prep<<<NN/256, 256>>>();
    prep_node<<<NN/256, 256>>>(pos, batch);
    prep_edge<<<EE/256, 256>>>(eidx);
    fin_cnt<<<NN/256, 256>>>();

    encoder1<<<NN, 128>>>(u, We1, be1);
    mlp16<<<NN/64, 256, MLP_SMEM_128>>>(t1, (const float*)0, We2, be2, (const float*)0, (const float*)0, h, 128, 0);

    for (int l = 0; l < LL; l++) {
        const float* Wm1l = Wm1 + (size_t)l * 283 * 128;
        const float* Wu1l = Wu1 + (size_t)l * 257 * 128;
        const float* Wm2l = Wm2 + (size_t)l * 128 * 128;
        const float* Wu2l = Wu2 + (size_t)l * 128 * 128;

        rkern<<<NN, 128>>>(u, Wm1l);
        mlp16<<<NN/64, 256, MLP_SMEM_128>>>(h, (const float*)0, Wm1l, bm1 + l*128, R, Wm1l + 282*128, P, 128, 1);
        mlp16<<<NN/64, 256, MLP_SMEM_128>>>(h, (const float*)0, Wm1l + 128*128, (const float*)0, R, (const float*)0, Q, 128, 2);

        zero_agg<<<(NN*HH/4)/256, 256>>>();
        edge_kernel<<<EE/64, 256, EDGE_SMEM>>>(eidx, Wm2l, bm2 + l*128);

        mlp16<<<NN/64, 256, MLP_SMEM_MAX>>>(h, agg, Wu1l, bu1 + l*128, (const float*)0, Wu1l + 256*128, t1, 256, 3);
        mlp16<<<NN/64, 256, MLP_SMEM_128>>>(t1, (const float*)0, Wu2l, bu2 + l*128, (const float*)0, (const float*)0, h, 128, 4);

        zero_stats<<<(BB*HH + 255)/256, 256>>>();
        norm_reduce<<<NN/128, 128>>>(batch);
        norm_apply<<<(NN*HH)/256, 256>>>(batch);
    }

    decoder<<<NN, 64>>>(u, Wc1, bc1, Wc2, bc2, out);
}